// round 1
// baseline (speedup 1.0000x reference)
#include <cuda_runtime.h>
#include <cuda_bf16.h>
#include <math.h>

// Problem dims (fixed for this bench)
#define BB 64
#define LL 2048
#define DD 1024
#define VV 50257
#define TOPK 5

#define LCHUNK 8           // L split into 8 chunks of 256
#define TN 64              // GEMM N tile (lexicon rows per block)
#define TK 32              // GEMM K tile
#define BSPAD 68           // padded Bs row stride (16B aligned, conflict-free reads)

// Scratch (device globals; no allocations allowed)
__device__ float g_part[LCHUNK][BB][DD];   // mean-pool partials (2 MB)
__device__ float g_tsT[DD][BB];            // transposed pooled embeddings (k-major)
__device__ float g_xnorm[BB];
__device__ float g_ynorm[VV];

// ---------------------------------------------------------------------------
// Kernel 1: mean-pool partial sums. grid=(LCHUNK, BB), block=1024 (one d each)
// ---------------------------------------------------------------------------
__global__ void __launch_bounds__(1024) mean_partial_kernel(const float* __restrict__ patch) {
    int d = threadIdx.x;
    int c = blockIdx.x;
    int b = blockIdx.y;
    const float* p = patch + ((size_t)b * LL + (size_t)c * (LL / LCHUNK)) * DD + d;
    float s = 0.f;
    #pragma unroll 8
    for (int l = 0; l < LL / LCHUNK; l++) {
        s += p[(size_t)l * DD];
    }
    g_part[c][b][d] = s;
}

// ---------------------------------------------------------------------------
// Kernel 2: finalize mean, write transposed ts, compute x norms.
// grid=BB, block=1024
// ---------------------------------------------------------------------------
__global__ void __launch_bounds__(1024) finalize_kernel() {
    int b = blockIdx.x;
    int d = threadIdx.x;
    float s = 0.f;
    #pragma unroll
    for (int c = 0; c < LCHUNK; c++) s += g_part[c][b][d];
    float ts = s * (1.0f / (float)LL);
    g_tsT[d][b] = ts;

    // block reduce ts*ts -> xnorm
    float val = ts * ts;
    #pragma unroll
    for (int o = 16; o; o >>= 1) val += __shfl_xor_sync(0xFFFFFFFFu, val, o);
    __shared__ float red[32];
    if ((d & 31) == 0) red[d >> 5] = val;
    __syncthreads();
    if (d < 32) {
        float v2 = red[d];
        #pragma unroll
        for (int o = 16; o; o >>= 1) v2 += __shfl_xor_sync(0xFFFFFFFFu, v2, o);
        if (d == 0) g_xnorm[b] = sqrtf(v2);
    }
}

// ---------------------------------------------------------------------------
// Kernel 3: lexicon row norms. grid=VV, block=256 (float4 per thread)
// ---------------------------------------------------------------------------
__global__ void __launch_bounds__(256) ynorm_kernel(const float* __restrict__ lex) {
    int v = blockIdx.x;
    int t = threadIdx.x;
    const float4* row = reinterpret_cast<const float4*>(lex + (size_t)v * DD);
    float4 f = row[t];
    float s = f.x * f.x + f.y * f.y + f.z * f.z + f.w * f.w;
    #pragma unroll
    for (int o = 16; o; o >>= 1) s += __shfl_xor_sync(0xFFFFFFFFu, s, o);
    __shared__ float red[8];
    if ((t & 31) == 0) red[t >> 5] = s;
    __syncthreads();
    if (t == 0) {
        float tot = 0.f;
        #pragma unroll
        for (int w = 0; w < 8; w++) tot += red[w];
        g_ynorm[v] = sqrtf(tot);
    }
}

// ---------------------------------------------------------------------------
// Kernel 4: similarity GEMM. dots[b][v] = ts[b,:] . lex[v,:], normalized.
// grid = ceil(VV/TN), block = 256. 64x64 output tile, 4x4 microtile.
// ---------------------------------------------------------------------------
__global__ void __launch_bounds__(256) gemm_kernel(const float* __restrict__ lex,
                                                   float* __restrict__ out_sim) {
    __shared__ float As[TK][BB];        // k-major ts tile (contiguous copy from g_tsT)
    __shared__ float Bs[TK][BSPAD];     // k-major lexicon tile (transposed on store)
    __shared__ float s_xn[BB];
    __shared__ float s_yn[TN];

    int tid = threadIdx.x;
    int v0 = blockIdx.x * TN;
    int tx = tid & 15;       // n direction
    int ty = tid >> 4;       // m direction

    if (tid < BB) s_xn[tid] = g_xnorm[tid];
    if (tid < TN) {
        int v = v0 + tid;
        s_yn[tid] = (v < VV) ? g_ynorm[v] : 1.f;
    }

    float acc[4][4];
    #pragma unroll
    for (int i = 0; i < 4; i++)
        #pragma unroll
        for (int j = 0; j < 4; j++) acc[i][j] = 0.f;

    for (int k0 = 0; k0 < DD; k0 += TK) {
        __syncthreads();
        // Load A tile: 2048 contiguous floats from g_tsT[k0..k0+31][*]
        {
            const float4* src = reinterpret_cast<const float4*>(&g_tsT[k0][0]);
            float4* dst = reinterpret_cast<float4*>(&As[0][0]);
            dst[tid]       = src[tid];
            dst[tid + 256] = src[tid + 256];
        }
        // Load B tile: 64 rows x 32 k, transpose into Bs[k][n]
        #pragma unroll
        for (int i = 0; i < 2; i++) {
            int idx4 = tid + i * 256;          // 0..511
            int n = idx4 >> 3;                 // 0..63
            int kq = (idx4 & 7) << 2;          // 0,4,...,28
            int v = v0 + n;
            float4 val = make_float4(0.f, 0.f, 0.f, 0.f);
            if (v < VV)
                val = *reinterpret_cast<const float4*>(&lex[(size_t)v * DD + k0 + kq]);
            Bs[kq + 0][n] = val.x;
            Bs[kq + 1][n] = val.y;
            Bs[kq + 2][n] = val.z;
            Bs[kq + 3][n] = val.w;
        }
        __syncthreads();
        #pragma unroll
        for (int k = 0; k < TK; k++) {
            float4 a = *reinterpret_cast<float4*>(&As[k][ty << 2]);
            float4 bv = *reinterpret_cast<float4*>(&Bs[k][tx << 2]);
            float av[4] = {a.x, a.y, a.z, a.w};
            float bw[4] = {bv.x, bv.y, bv.z, bv.w};
            #pragma unroll
            for (int i = 0; i < 4; i++)
                #pragma unroll
                for (int j = 0; j < 4; j++)
                    acc[i][j] = fmaf(av[i], bw[j], acc[i][j]);
        }
    }

    // Epilogue: normalize and store (scalar stores: V is odd, no vec alignment)
    #pragma unroll
    for (int i = 0; i < 4; i++) {
        int m = (ty << 2) + i;
        float xn = s_xn[m];
        #pragma unroll
        for (int j = 0; j < 4; j++) {
            int n = (tx << 2) + j;
            int v = v0 + n;
            if (v < VV) {
                float den = fmaxf(xn * s_yn[n], 1e-8f);
                out_sim[(size_t)m * VV + v] = acc[i][j] / den;
            }
        }
    }
}

// ---------------------------------------------------------------------------
// Kernel 5: top-k (5 masked argmax passes) + gather. grid=BB, block=1024
// Tie-break: lowest index wins (matches jax.lax.top_k).
// ---------------------------------------------------------------------------
__global__ void __launch_bounds__(1024) topk_kernel(const float* __restrict__ lex,
                                                    const float* __restrict__ sim,
                                                    float* __restrict__ out_topk) {
    int b = blockIdx.x;
    int t = threadIdx.x;
    __shared__ float s_val[32];
    __shared__ int   s_idx[32];
    __shared__ int   sel[TOPK];

    const float* row = sim + (size_t)b * VV;

    for (int j = 0; j < TOPK; j++) {
        float bv = -1e30f;
        int bi = 0x7FFFFFFF;
        for (int v = t; v < VV; v += 1024) {
            bool skip = false;
            #pragma unroll
            for (int jj = 0; jj < TOPK; jj++)
                if (jj < j && sel[jj] == v) skip = true;
            float x = skip ? -1e30f : row[v];
            if (x > bv || (x == bv && v < bi)) { bv = x; bi = v; }
        }
        #pragma unroll
        for (int o = 16; o; o >>= 1) {
            float ov = __shfl_xor_sync(0xFFFFFFFFu, bv, o);
            int   oi = __shfl_xor_sync(0xFFFFFFFFu, bi, o);
            if (ov > bv || (ov == bv && oi < bi)) { bv = ov; bi = oi; }
        }
        if ((t & 31) == 0) { s_val[t >> 5] = bv; s_idx[t >> 5] = bi; }
        __syncthreads();
        if (t == 0) {
            for (int w = 1; w < 32; w++) {
                if (s_val[w] > bv || (s_val[w] == bv && s_idx[w] < bi)) {
                    bv = s_val[w]; bi = s_idx[w];
                }
            }
            sel[j] = bi;
        }
        __syncthreads();
    }

    // Gather top-k lexicon rows
    for (int j = 0; j < TOPK; j++) {
        const float* src = lex + (size_t)sel[j] * DD;
        float* dst = out_topk + ((size_t)b * TOPK + j) * DD;
        for (int d = t; d < DD; d += 1024) dst[d] = src[d];
    }
}

// ---------------------------------------------------------------------------
extern "C" void kernel_launch(void* const* d_in, const int* in_sizes, int n_in,
                              void* d_out, int out_size) {
    const float* patch = (const float*)d_in[0];
    const float* lex   = (const float*)d_in[1];
    float* out      = (float*)d_out;
    float* out_topk = out;                                  // [64][5][1024]
    float* out_sim  = out + (size_t)BB * TOPK * DD;         // [64][50257]

    mean_partial_kernel<<<dim3(LCHUNK, BB), 1024>>>(patch);
    finalize_kernel<<<BB, 1024>>>();
    ynorm_kernel<<<VV, 256>>>(lex);
    gemm_kernel<<<(VV + TN - 1) / TN, 256>>>(lex, out_sim);
    topk_kernel<<<BB, 1024>>>(lex, out_sim, out_topk);
}